// round 1
// baseline (speedup 1.0000x reference)
#include <cuda_runtime.h>
#include <cuda_bf16.h>
#include <math.h>

// Problem constants
#define B_SZ   2
#define S_LEN  2048
#define E_DIM  1024
#define H_NUM  16
#define D_HEAD 64
#define ALPHA  0.5f

// Scratch (device globals — no allocation allowed)
__device__ float g_Q[B_SZ * S_LEN * E_DIM];
__device__ float g_K[B_SZ * S_LEN * E_DIM];
__device__ float g_V[B_SZ * S_LEN * E_DIM];
__device__ float g_A[B_SZ * S_LEN * E_DIM];

// ---------------------------------------------------------------------------
// GEMM: C[M,N] = A[M,K] @ W[N,K]^T   (y = x @ W.T, both row-major)
// Tiles: 64x64x16, 256 threads, 4x4 microtile per thread.
// ---------------------------------------------------------------------------
__global__ __launch_bounds__(256)
void gemm_xwt(const float* __restrict__ A, const float* __restrict__ W,
              float* __restrict__ C, int M, int N, int K)
{
    __shared__ float As[16][68];   // [k][m], padded, float4-aligned rows
    __shared__ float Ws[16][68];   // [k][n]

    const int t  = threadIdx.x;
    const int bm = blockIdx.y * 64;
    const int bn = blockIdx.x * 64;

    // loader mapping: each thread loads one float4 (4 consecutive k) per tile
    const int lm = t >> 2;          // row within tile (0..63)
    const int kg = (t & 3) * 4;     // k-group (0,4,8,12)

    const float* Aload = A + (size_t)(bm + lm) * K + kg;
    const float* Wload = W + (size_t)(bn + lm) * K + kg;

    // compute mapping: 16x16 thread grid of 4x4 microtiles
    const int tm = (t >> 4) * 4;    // row offset
    const int tn = (t & 15) * 4;    // col offset

    float acc[4][4];
#pragma unroll
    for (int i = 0; i < 4; i++)
#pragma unroll
        for (int j = 0; j < 4; j++) acc[i][j] = 0.0f;

    for (int k0 = 0; k0 < K; k0 += 16) {
        float4 av = *(const float4*)(Aload + k0);
        float4 wv = *(const float4*)(Wload + k0);
        As[kg + 0][lm] = av.x; As[kg + 1][lm] = av.y;
        As[kg + 2][lm] = av.z; As[kg + 3][lm] = av.w;
        Ws[kg + 0][lm] = wv.x; Ws[kg + 1][lm] = wv.y;
        Ws[kg + 2][lm] = wv.z; Ws[kg + 3][lm] = wv.w;
        __syncthreads();

#pragma unroll
        for (int k = 0; k < 16; k++) {
            float4 a = *(const float4*)&As[k][tm];
            float4 b = *(const float4*)&Ws[k][tn];
            float ar[4] = {a.x, a.y, a.z, a.w};
            float br[4] = {b.x, b.y, b.z, b.w};
#pragma unroll
            for (int i = 0; i < 4; i++)
#pragma unroll
                for (int j = 0; j < 4; j++)
                    acc[i][j] = fmaf(ar[i], br[j], acc[i][j]);
        }
        __syncthreads();
    }

#pragma unroll
    for (int i = 0; i < 4; i++) {
        float4 o = make_float4(acc[i][0], acc[i][1], acc[i][2], acc[i][3]);
        *(float4*)&C[(size_t)(bm + tm + i) * N + bn + tn] = o;
    }
}

// ---------------------------------------------------------------------------
// Flash-attention style: per block = 64 queries of one (b,h).
// Streams 32 KV tiles of 64 keys, online softmax.
// scores = QK^T/8 + mirror bias; masked keys -> -1e30.
// ---------------------------------------------------------------------------
__global__ __launch_bounds__(256)
void attn_kernel(const unsigned int* __restrict__ mask, float* __restrict__ out)
{
    extern __shared__ float sm[];
    float* Qs   = sm;                // [64][64]
    float* Ks   = Qs + 64 * 64;      // [64][65]  (padded)
    float* Vs   = Ks + 64 * 65;      // [64][64]
    float* Ps   = Vs + 64 * 64;      // [64][65]  (padded)
    float* mrow = Ps + 64 * 65;      // [64] running max
    float* lrow = mrow + 64;         // [64] running sum
    float* crow = lrow + 64;         // [64] correction factor
    float* madd = crow + 64;         // [64] mask additive per key

    const int t  = threadIdx.x;
    const int q0 = blockIdx.x * 64;
    const int h  = blockIdx.y;
    const int b  = blockIdx.z;

    const int tm = (t >> 4) * 4;     // query rows (scores) / query rows (PV)
    const int tn = (t & 15) * 4;     // key cols (scores) / d cols (PV)

    // Load Q tile: [64 queries][64 dims]
#pragma unroll
    for (int g = 0; g < 4; g++) {
        int slot = t + g * 256;          // 1024 float4 slots? -> 64 rows * 16 groups
        int row = slot >> 4;
        int dg  = (slot & 15) * 4;
        float4 v = *(const float4*)&g_Q[((size_t)(b * S_LEN + q0 + row)) * E_DIM + h * D_HEAD + dg];
        *(float4*)&Qs[row * 64 + dg] = v;
    }
    if (t < 64) { mrow[t] = -1e30f; lrow[t] = 0.0f; }

    float o[4][4];
#pragma unroll
    for (int i = 0; i < 4; i++)
#pragma unroll
        for (int j = 0; j < 4; j++) o[i][j] = 0.0f;

    for (int kt = 0; kt < S_LEN / 64; kt++) {
        const int k0 = kt * 64;
        __syncthreads();   // protect shared from previous iteration's readers

        // Load K tile (padded rows) and V tile
#pragma unroll
        for (int g = 0; g < 4; g++) {
            int slot = t + g * 256;
            int row = slot >> 4;
            int dg  = (slot & 15) * 4;
            size_t gofs = ((size_t)(b * S_LEN + k0 + row)) * E_DIM + h * D_HEAD + dg;
            float4 kv = *(const float4*)&g_K[gofs];
            Ks[row * 65 + dg + 0] = kv.x;
            Ks[row * 65 + dg + 1] = kv.y;
            Ks[row * 65 + dg + 2] = kv.z;
            Ks[row * 65 + dg + 3] = kv.w;
            float4 vv = *(const float4*)&g_V[gofs];
            *(float4*)&Vs[row * 64 + dg] = vv;
        }
        if (t < 64)
            madd[t] = (mask[b * S_LEN + k0 + t] != 0u) ? -1e30f : 0.0f;
        __syncthreads();

        // Scores: s[i][j] = Q[tm+i] . K[tn+j]
        float s[4][4];
#pragma unroll
        for (int i = 0; i < 4; i++)
#pragma unroll
            for (int j = 0; j < 4; j++) s[i][j] = 0.0f;

#pragma unroll 4
        for (int d = 0; d < 64; d++) {
            float qv[4], kv[4];
#pragma unroll
            for (int i = 0; i < 4; i++) qv[i] = Qs[(tm + i) * 64 + d];
#pragma unroll
            for (int j = 0; j < 4; j++) kv[j] = Ks[(tn + j) * 65 + d];
#pragma unroll
            for (int i = 0; i < 4; i++)
#pragma unroll
                for (int j = 0; j < 4; j++)
                    s[i][j] = fmaf(qv[i], kv[j], s[i][j]);
        }

        // scale + mirror bias + mask, write raw scores to Ps
#pragma unroll
        for (int i = 0; i < 4; i++) {
            int iq = q0 + tm + i;
            float target = (float)(S_LEN - 1 - iq);
#pragma unroll
            for (int j = 0; j < 4; j++) {
                int jk = k0 + tn + j;
                float bias = -ALPHA * fabsf((float)jk - target) * (1.0f / (float)S_LEN);
                Ps[(tm + i) * 65 + tn + j] = s[i][j] * 0.125f + bias + madd[tn + j];
            }
        }
        __syncthreads();

        // Row max (64 threads, padded rows -> conflict-free)
        if (t < 64) {
            float mx = -1e30f;
#pragma unroll 8
            for (int c = 0; c < 64; c++) mx = fmaxf(mx, Ps[t * 65 + c]);
            float mold = mrow[t];
            float mnew = fmaxf(mold, mx);
            mrow[t] = mnew;
            crow[t] = __expf(mold - mnew);
        }
        __syncthreads();

        // exp in place + rescale O accumulators
#pragma unroll
        for (int i = 0; i < 4; i++) {
            float mi = mrow[tm + i];
            float ci = crow[tm + i];
#pragma unroll
            for (int j = 0; j < 4; j++) {
                int idx = (tm + i) * 65 + tn + j;
                Ps[idx] = __expf(Ps[idx] - mi);
                o[i][j] *= ci;
            }
        }
        __syncthreads();

        // Row sum, update l
        if (t < 64) {
            float sum = 0.0f;
#pragma unroll 8
            for (int c = 0; c < 64; c++) sum += Ps[t * 65 + c];
            lrow[t] = lrow[t] * crow[t] + sum;
        }

        // O += P @ V   (tm = query rows, tn = d cols here)
#pragma unroll 4
        for (int k = 0; k < 64; k++) {
            float pv[4];
#pragma unroll
            for (int i = 0; i < 4; i++) pv[i] = Ps[(tm + i) * 65 + k];
            float4 vv = *(const float4*)&Vs[k * 64 + tn];
            float vr[4] = {vv.x, vv.y, vv.z, vv.w};
#pragma unroll
            for (int i = 0; i < 4; i++)
#pragma unroll
                for (int j = 0; j < 4; j++)
                    o[i][j] = fmaf(pv[i], vr[j], o[i][j]);
        }
    }
    __syncthreads();

    // Normalize and write to attention output [B,S,E] (head h occupies cols h*64..)
#pragma unroll
    for (int i = 0; i < 4; i++) {
        float inv = 1.0f / lrow[tm + i];
        float4 ov = make_float4(o[i][0] * inv, o[i][1] * inv, o[i][2] * inv, o[i][3] * inv);
        *(float4*)&out[((size_t)(b * S_LEN + q0 + tm + i)) * E_DIM + h * D_HEAD + tn] = ov;
    }
}

// ---------------------------------------------------------------------------
extern "C" void kernel_launch(void* const* d_in, const int* in_sizes, int n_in,
                              void* d_out, int out_size)
{
    const float* x    = (const float*)d_in[0];
    const float* Wq   = (const float*)d_in[1];
    const float* Wk   = (const float*)d_in[2];
    const float* Wv   = (const float*)d_in[3];
    const float* Wo   = (const float*)d_in[4];
    const unsigned int* mask = (const unsigned int*)d_in[5];
    float* out = (float*)d_out;

    float *q_ptr, *k_ptr, *v_ptr, *a_ptr;
    cudaGetSymbolAddress((void**)&q_ptr, g_Q);
    cudaGetSymbolAddress((void**)&k_ptr, g_K);
    cudaGetSymbolAddress((void**)&v_ptr, g_V);
    cudaGetSymbolAddress((void**)&a_ptr, g_A);

    const int M = B_SZ * S_LEN;   // 4096
    const int N = E_DIM;          // 1024
    const int K = E_DIM;          // 1024

    dim3 gblk(256);
    dim3 ggrid(N / 64, M / 64);

    // QKV projections
    gemm_xwt<<<ggrid, gblk>>>(x, Wq, q_ptr, M, N, K);
    gemm_xwt<<<ggrid, gblk>>>(x, Wk, k_ptr, M, N, K);
    gemm_xwt<<<ggrid, gblk>>>(x, Wv, v_ptr, M, N, K);

    // Attention
    const int smem_bytes = (64*64 + 64*65 + 64*64 + 64*65 + 4*64) * sizeof(float);
    cudaFuncSetAttribute(attn_kernel, cudaFuncAttributeMaxDynamicSharedMemorySize, smem_bytes);
    dim3 agrid(S_LEN / 64, H_NUM, B_SZ);
    attn_kernel<<<agrid, 256, smem_bytes>>>(mask, a_ptr);

    // Output projection
    gemm_xwt<<<ggrid, gblk>>>(a_ptr, Wo, out, M, N, K);
}

// round 3
// speedup vs baseline: 2.6697x; 2.6697x over previous
#include <cuda_runtime.h>
#include <cuda_bf16.h>
#include <cstdint>
#include <math.h>

// Problem constants
#define B_SZ   2
#define S_LEN  2048
#define E_DIM  1024
#define H_NUM  16
#define D_HEAD 64
#define ALPHA  0.5f
#define LOG2E  1.4426950408889634f

// GEMM tiling
#define GM 4096
#define GN 1024
#define GK 1024

// Scratch (device globals — no allocation allowed)
__device__ float g_Q[B_SZ * S_LEN * E_DIM];
__device__ float g_K[B_SZ * S_LEN * E_DIM];
__device__ float g_V[B_SZ * S_LEN * E_DIM];
__device__ float g_A[B_SZ * S_LEN * E_DIM];

// ---------------------------------------------------------------------------
// Helpers
// ---------------------------------------------------------------------------
static __device__ __forceinline__ float to_tf32(float f) {
    uint32_t u;
    asm("cvt.rna.tf32.f32 %0, %1;" : "=r"(u) : "f"(f));
    return __uint_as_float(u);
}

// D = A(16x8 row) @ B(8x8 col) + C, tf32 in, f32 out. d may alias c.
static __device__ __forceinline__ void mma_tf32(float* d,
                                                const float a0, const float a1,
                                                const float a2, const float a3,
                                                const float b0, const float b1) {
    asm volatile(
        "mma.sync.aligned.m16n8k8.row.col.f32.tf32.tf32.f32 "
        "{%0,%1,%2,%3}, {%4,%5,%6,%7}, {%8,%9}, {%0,%1,%2,%3};"
        : "+f"(d[0]), "+f"(d[1]), "+f"(d[2]), "+f"(d[3])
        : "r"(__float_as_uint(a0)), "r"(__float_as_uint(a1)),
          "r"(__float_as_uint(a2)), "r"(__float_as_uint(a3)),
          "r"(__float_as_uint(b0)), "r"(__float_as_uint(b1)));
}

// ---------------------------------------------------------------------------
// TF32 tensor-core GEMM: C[M,N] = A[M,K] @ W[N,K]^T  (both row-major)
// CTA 128x128, 256 threads (8 warps as 4x2), warp tile 32x64, K-chunk 32.
// SMEM stride 36 floats (36 % 32 == 4 -> conflict-free fragment loads).
// ---------------------------------------------------------------------------
#define GST 36
#define GEMM_SMEM (4 * 128 * GST * 4)   // 2 bufs x (A + W) tiles

__global__ __launch_bounds__(256)
void gemm_tc(const float* __restrict__ A, const float* __restrict__ W,
             float* __restrict__ C)
{
    extern __shared__ float smf[];
    float* sA[2] = { smf,                smf + 2 * 128 * GST };
    float* sW[2] = { smf + 128 * GST,    smf + 3 * 128 * GST };

    const int t     = threadIdx.x;
    const int w     = t >> 5;
    const int lane  = t & 31;
    const int g     = lane >> 2;       // group id (0..7)
    const int t4    = lane & 3;        // thread in group
    const int wm    = w >> 1;          // 0..3
    const int wn    = w & 1;           // 0..1
    const int m0    = wm * 32;
    const int n0w   = wn * 64;
    const int bm    = blockIdx.y * 128;
    const int bn    = blockIdx.x * 128;

    // loader mapping: 1024 float4 slots, 4 per thread
    const int lrow = (t * 4) >> 5;         // not used; keep explicit below

    float c[2][8][4];
#pragma unroll
    for (int mf = 0; mf < 2; mf++)
#pragma unroll
        for (int nf = 0; nf < 8; nf++)
#pragma unroll
            for (int r = 0; r < 4; r++) c[mf][nf][r] = 0.0f;

    float4 pa[4], pw[4];
    // prefetch chunk 0
#pragma unroll
    for (int i = 0; i < 4; i++) {
        int idx = i * 256 + t;
        int row = idx >> 3;
        int f4  = idx & 7;
        pa[i] = *(const float4*)&A[(size_t)(bm + row) * GK + f4 * 4];
        pw[i] = *(const float4*)&W[(size_t)(bn + row) * GK + f4 * 4];
    }

    for (int ch = 0; ch < GK / 32; ch++) {
        const int buf = ch & 1;
        // store prefetched chunk to smem (tf32-converted)
#pragma unroll
        for (int i = 0; i < 4; i++) {
            int idx = i * 256 + t;
            int row = idx >> 3;
            int f4  = idx & 7;
            float* da = &sA[buf][row * GST + f4 * 4];
            da[0] = to_tf32(pa[i].x); da[1] = to_tf32(pa[i].y);
            da[2] = to_tf32(pa[i].z); da[3] = to_tf32(pa[i].w);
            float* dw = &sW[buf][row * GST + f4 * 4];
            dw[0] = to_tf32(pw[i].x); dw[1] = to_tf32(pw[i].y);
            dw[2] = to_tf32(pw[i].z); dw[3] = to_tf32(pw[i].w);
        }
        __syncthreads();

        if (ch < GK / 32 - 1) {
            const int k0g = (ch + 1) * 32;
#pragma unroll
            for (int i = 0; i < 4; i++) {
                int idx = i * 256 + t;
                int row = idx >> 3;
                int f4  = idx & 7;
                pa[i] = *(const float4*)&A[(size_t)(bm + row) * GK + k0g + f4 * 4];
                pw[i] = *(const float4*)&W[(size_t)(bn + row) * GK + k0g + f4 * 4];
            }
        }

        // compute chunk
        const float* a_s = sA[buf];
        const float* w_s = sW[buf];
#pragma unroll
        for (int ks = 0; ks < 4; ks++) {
            const int k0 = ks * 8;
            float a[2][4];
#pragma unroll
            for (int mf = 0; mf < 2; mf++) {
                int row = m0 + mf * 16 + g;
                a[mf][0] = a_s[row * GST + k0 + t4];
                a[mf][1] = a_s[(row + 8) * GST + k0 + t4];
                a[mf][2] = a_s[row * GST + k0 + t4 + 4];
                a[mf][3] = a_s[(row + 8) * GST + k0 + t4 + 4];
            }
#pragma unroll
            for (int nf = 0; nf < 8; nf++) {
                int nrow = n0w + nf * 8 + g;
                float b0 = w_s[nrow * GST + k0 + t4];
                float b1 = w_s[nrow * GST + k0 + t4 + 4];
                mma_tf32(c[0][nf], a[0][0], a[0][1], a[0][2], a[0][3], b0, b1);
                mma_tf32(c[1][nf], a[1][0], a[1][1], a[1][2], a[1][3], b0, b1);
            }
        }
    }

    // epilogue: float2 stores
#pragma unroll
    for (int mf = 0; mf < 2; mf++) {
        int row = bm + m0 + mf * 16 + g;
#pragma unroll
        for (int nf = 0; nf < 8; nf++) {
            int col = bn + n0w + nf * 8 + 2 * t4;
            *(float2*)&C[(size_t)row * GN + col] =
                make_float2(c[mf][nf][0], c[mf][nf][1]);
            *(float2*)&C[(size_t)(row + 8) * GN + col] =
                make_float2(c[mf][nf][2], c[mf][nf][3]);
        }
    }
}

// ---------------------------------------------------------------------------
// Tensor-core flash attention (TF32 mma, exp2-domain online softmax).
// Block: 128 threads (4 warps). Per block: one (b,h), 64 query rows.
// Warp w owns query rows [w*16, w*16+16). KV streamed in 64-key tiles.
// ---------------------------------------------------------------------------
#define AST 68   // smem row stride (floats); 68 % 32 == 4 -> conflict-free
#define ATT_SMEM ((4 * 64 * AST + 64) * 4)

__global__ __launch_bounds__(128)
void attn_tc(const unsigned int* __restrict__ mask, float* __restrict__ out)
{
    extern __shared__ float smf[];
    float* Qs   = smf;
    float* Ks   = Qs + 64 * AST;
    float* Vs   = Ks + 64 * AST;
    float* Ps   = Vs + 64 * AST;
    float* madd = Ps + 64 * AST;

    const int t    = threadIdx.x;
    const int w    = t >> 5;
    const int lane = t & 31;
    const int g    = lane >> 2;
    const int t4   = lane & 3;
    const int q0   = blockIdx.x * 64;
    const int h    = blockIdx.y;
    const int b    = blockIdx.z;
    const int m0   = w * 16;

    const float QSCALE = 0.125f * LOG2E;             // 1/sqrt(64) * log2(e)
    const float BSC    = ALPHA * LOG2E / (float)S_LEN;

    // Load Q tile (scaled + tf32)
#pragma unroll
    for (int i = 0; i < 8; i++) {
        int idx = i * 128 + t;
        int row = idx >> 4;
        int dg  = (idx & 15) * 4;
        float4 v = *(const float4*)&g_Q[((size_t)(b * S_LEN + q0 + row)) * E_DIM + h * D_HEAD + dg];
        float* d = &Qs[row * AST + dg];
        d[0] = to_tf32(v.x * QSCALE); d[1] = to_tf32(v.y * QSCALE);
        d[2] = to_tf32(v.z * QSCALE); d[3] = to_tf32(v.w * QSCALE);
    }

    float o[8][4];
#pragma unroll
    for (int nf = 0; nf < 8; nf++)
#pragma unroll
        for (int r = 0; r < 4; r++) o[nf][r] = 0.0f;

    float mrow0 = -1e30f, mrow1 = -1e30f;
    float lrow0 = 0.0f,  lrow1 = 0.0f;

    const int iq0 = q0 + m0 + g;
    const int iq1 = iq0 + 8;
    const float tgt0 = (float)(S_LEN - 1 - iq0);
    const float tgt1 = (float)(S_LEN - 1 - iq1);

    for (int kt = 0; kt < S_LEN / 64; kt++) {
        const int k0g = kt * 64;
        __syncthreads();
        // Load K, V tiles (tf32) + mask additive
#pragma unroll
        for (int i = 0; i < 8; i++) {
            int idx = i * 128 + t;
            int row = idx >> 4;
            int dg  = (idx & 15) * 4;
            size_t gofs = ((size_t)(b * S_LEN + k0g + row)) * E_DIM + h * D_HEAD + dg;
            float4 kv = *(const float4*)&g_K[gofs];
            float* dk = &Ks[row * AST + dg];
            dk[0] = to_tf32(kv.x); dk[1] = to_tf32(kv.y);
            dk[2] = to_tf32(kv.z); dk[3] = to_tf32(kv.w);
            float4 vv = *(const float4*)&g_V[gofs];
            float* dv = &Vs[row * AST + dg];
            dv[0] = to_tf32(vv.x); dv[1] = to_tf32(vv.y);
            dv[2] = to_tf32(vv.z); dv[3] = to_tf32(vv.w);
        }
        if (t < 64)
            madd[t] = (mask[b * S_LEN + k0g + t] != 0u) ? -1e30f : 0.0f;
        __syncthreads();

        // ---- S = Qs @ Ks^T (in exp2 domain; scale folded into Q) ----
        float sc[8][4];
#pragma unroll
        for (int nf = 0; nf < 8; nf++)
#pragma unroll
            for (int r = 0; r < 4; r++) sc[nf][r] = 0.0f;

#pragma unroll
        for (int ks = 0; ks < 8; ks++) {
            const int k0 = ks * 8;
            int row = m0 + g;
            float a0 = Qs[row * AST + k0 + t4];
            float a1 = Qs[(row + 8) * AST + k0 + t4];
            float a2 = Qs[row * AST + k0 + t4 + 4];
            float a3 = Qs[(row + 8) * AST + k0 + t4 + 4];
#pragma unroll
            for (int nf = 0; nf < 8; nf++) {
                int nrow = nf * 8 + g;
                float b0 = Ks[nrow * AST + k0 + t4];
                float b1 = Ks[nrow * AST + k0 + t4 + 4];
                mma_tf32(sc[nf], a0, a1, a2, a3, b0, b1);
            }
        }

        // ---- bias + mask ----
#pragma unroll
        for (int nf = 0; nf < 8; nf++) {
            int jc = nf * 8 + 2 * t4;
            float jk0 = (float)(k0g + jc);
            float jk1 = jk0 + 1.0f;
            float ma0 = madd[jc], ma1 = madd[jc + 1];
            sc[nf][0] += -BSC * fabsf(jk0 - tgt0) + ma0;
            sc[nf][1] += -BSC * fabsf(jk1 - tgt0) + ma1;
            sc[nf][2] += -BSC * fabsf(jk0 - tgt1) + ma0;
            sc[nf][3] += -BSC * fabsf(jk1 - tgt1) + ma1;
        }

        // ---- row max (quad shfl) ----
        float mx0 = -1e30f, mx1 = -1e30f;
#pragma unroll
        for (int nf = 0; nf < 8; nf++) {
            mx0 = fmaxf(mx0, fmaxf(sc[nf][0], sc[nf][1]));
            mx1 = fmaxf(mx1, fmaxf(sc[nf][2], sc[nf][3]));
        }
        mx0 = fmaxf(mx0, __shfl_xor_sync(0xffffffffu, mx0, 1));
        mx0 = fmaxf(mx0, __shfl_xor_sync(0xffffffffu, mx0, 2));
        mx1 = fmaxf(mx1, __shfl_xor_sync(0xffffffffu, mx1, 1));
        mx1 = fmaxf(mx1, __shfl_xor_sync(0xffffffffu, mx1, 2));

        float mnew0 = fmaxf(mrow0, mx0);
        float mnew1 = fmaxf(mrow1, mx1);
        float c0 = exp2f(mrow0 - mnew0);
        float c1 = exp2f(mrow1 - mnew1);
        mrow0 = mnew0; mrow1 = mnew1;

        // ---- p = exp2(s - m), partial sums, write P to smem (tf32) ----
        float s0 = 0.0f, s1 = 0.0f;
#pragma unroll
        for (int nf = 0; nf < 8; nf++) {
            float p0 = exp2f(sc[nf][0] - mnew0);
            float p1 = exp2f(sc[nf][1] - mnew0);
            float p2 = exp2f(sc[nf][2] - mnew1);
            float p3 = exp2f(sc[nf][3] - mnew1);
            s0 += p0 + p1;
            s1 += p2 + p3;
            int col = nf * 8 + 2 * t4;
            *(float2*)&Ps[(m0 + g) * AST + col]     = make_float2(to_tf32(p0), to_tf32(p1));
            *(float2*)&Ps[(m0 + g + 8) * AST + col] = make_float2(to_tf32(p2), to_tf32(p3));
        }
        s0 += __shfl_xor_sync(0xffffffffu, s0, 1);
        s0 += __shfl_xor_sync(0xffffffffu, s0, 2);
        s1 += __shfl_xor_sync(0xffffffffu, s1, 1);
        s1 += __shfl_xor_sync(0xffffffffu, s1, 2);
        lrow0 = lrow0 * c0 + s0;
        lrow1 = lrow1 * c1 + s1;

        // ---- rescale O ----
#pragma unroll
        for (int nf = 0; nf < 8; nf++) {
            o[nf][0] *= c0; o[nf][1] *= c0;
            o[nf][2] *= c1; o[nf][3] *= c1;
        }
        __syncwarp();

        // ---- O += P @ V ----
#pragma unroll
        for (int ks = 0; ks < 8; ks++) {
            const int k0 = ks * 8;
            int row = m0 + g;
            float a0 = Ps[row * AST + k0 + t4];
            float a1 = Ps[(row + 8) * AST + k0 + t4];
            float a2 = Ps[row * AST + k0 + t4 + 4];
            float a3 = Ps[(row + 8) * AST + k0 + t4 + 4];
#pragma unroll
            for (int nf = 0; nf < 8; nf++) {
                int n0 = nf * 8 + g;
                float b0 = Vs[(k0 + t4) * AST + n0];
                float b1 = Vs[(k0 + t4 + 4) * AST + n0];
                mma_tf32(o[nf], a0, a1, a2, a3, b0, b1);
            }
        }
        __syncwarp();   // Ps/Vs reads done before next tile overwrites
    }

    // ---- finalize: O / l, write to g_A ----
    float inv0 = 1.0f / lrow0;
    float inv1 = 1.0f / lrow1;
#pragma unroll
    for (int nf = 0; nf < 8; nf++) {
        int col = h * D_HEAD + nf * 8 + 2 * t4;
        size_t r0 = ((size_t)(b * S_LEN + q0 + m0 + g)) * E_DIM + col;
        size_t r1 = r0 + 8 * E_DIM;
        *(float2*)&out[r0] = make_float2(o[nf][0] * inv0, o[nf][1] * inv0);
        *(float2*)&out[r1] = make_float2(o[nf][2] * inv1, o[nf][3] * inv1);
    }
}

// ---------------------------------------------------------------------------
extern "C" void kernel_launch(void* const* d_in, const int* in_sizes, int n_in,
                              void* d_out, int out_size)
{
    const float* x    = (const float*)d_in[0];
    const float* Wq   = (const float*)d_in[1];
    const float* Wk   = (const float*)d_in[2];
    const float* Wv   = (const float*)d_in[3];
    const float* Wo   = (const float*)d_in[4];
    const unsigned int* mask = (const unsigned int*)d_in[5];
    float* out = (float*)d_out;

    float *q_ptr, *k_ptr, *v_ptr, *a_ptr;
    cudaGetSymbolAddress((void**)&q_ptr, g_Q);
    cudaGetSymbolAddress((void**)&k_ptr, g_K);
    cudaGetSymbolAddress((void**)&v_ptr, g_V);
    cudaGetSymbolAddress((void**)&a_ptr, g_A);

    cudaFuncSetAttribute(gemm_tc, cudaFuncAttributeMaxDynamicSharedMemorySize, GEMM_SMEM);
    cudaFuncSetAttribute(attn_tc, cudaFuncAttributeMaxDynamicSharedMemorySize, ATT_SMEM);

    dim3 ggrid(GN / 128, GM / 128);   // (8, 32)
    gemm_tc<<<ggrid, 256, GEMM_SMEM>>>(x, Wq, q_ptr);
    gemm_tc<<<ggrid, 256, GEMM_SMEM>>>(x, Wk, k_ptr);
    gemm_tc<<<ggrid, 256, GEMM_SMEM>>>(x, Wv, v_ptr);

    dim3 agrid(S_LEN / 64, H_NUM, B_SZ);
    attn_tc<<<agrid, 128, ATT_SMEM>>>(mask, a_ptr);

    gemm_tc<<<ggrid, 256, GEMM_SMEM>>>(a_ptr, Wo, out);
}

// round 4
// speedup vs baseline: 4.4020x; 1.6489x over previous
#include <cuda_runtime.h>
#include <cuda_bf16.h>
#include <cstdint>
#include <math.h>

// Problem constants
#define B_SZ   2
#define S_LEN  2048
#define E_DIM  1024
#define H_NUM  16
#define D_HEAD 64
#define ALPHA  0.5f
#define LOG2E  1.4426950408889634f

#define GM 4096
#define GN 1024
#define GK 1024

// Scratch (device globals — allocation-free)
__device__ float g_X [GM * GK];          // x, tf32
__device__ float g_Wq[GN * GK];          // Wq * QSCALE, tf32
__device__ float g_Wk[GN * GK];
__device__ float g_Wv[GN * GK];
__device__ float g_Wo[GN * GK];
__device__ float g_Q [GM * GN];          // tf32, pre-scaled
__device__ float g_K [GM * GN];          // tf32
__device__ float g_V [GM * GN];          // tf32
__device__ float g_A [GM * GN];          // attention out, tf32

// ---------------------------------------------------------------------------
// Helpers
// ---------------------------------------------------------------------------
static __device__ __forceinline__ uint32_t smem_u32(const void* p) {
    uint32_t a;
    asm("{ .reg .u64 t; cvta.to.shared.u64 t, %1; cvt.u32.u64 %0, t; }" : "=r"(a) : "l"(p));
    return a;
}
static __device__ __forceinline__ float to_tf32(float f) {
    uint32_t u;
    asm("cvt.rna.tf32.f32 %0, %1;" : "=r"(u) : "f"(f));
    return __uint_as_float(u);
}
static __device__ __forceinline__ float ex2(float x) {
    float y;
    asm("ex2.approx.f32 %0, %1;" : "=f"(y) : "f"(x));
    return y;
}
static __device__ __forceinline__ void cp16(uint32_t dst, const void* src) {
    asm volatile("cp.async.cg.shared.global [%0], [%1], 16;" :: "r"(dst), "l"(src));
}
static __device__ __forceinline__ void cp_commit() {
    asm volatile("cp.async.commit_group;" ::: "memory");
}
// D += A(16x8) @ B(8x8), tf32
static __device__ __forceinline__ void mma_tf32(float* d,
                                                const float a0, const float a1,
                                                const float a2, const float a3,
                                                const float b0, const float b1) {
    asm volatile(
        "mma.sync.aligned.m16n8k8.row.col.f32.tf32.tf32.f32 "
        "{%0,%1,%2,%3}, {%4,%5,%6,%7}, {%8,%9}, {%0,%1,%2,%3};"
        : "+f"(d[0]), "+f"(d[1]), "+f"(d[2]), "+f"(d[3])
        : "r"(__float_as_uint(a0)), "r"(__float_as_uint(a1)),
          "r"(__float_as_uint(a2)), "r"(__float_as_uint(a3)),
          "r"(__float_as_uint(b0)), "r"(__float_as_uint(b1)));
}
// XOR swizzles (float-index domain)
static __device__ __forceinline__ int fswz32(int f) { return f ^ ((f >> 3) & 0x1C); }   // 32-float rows
static __device__ __forceinline__ int fswz64(int f) { return f ^ ((f >> 4) & 0x1C); }   // 64-float rows

// ---------------------------------------------------------------------------
// Pre-convert inputs to TF32 (scale folded for Wq)
// z: 0=x->g_X  1=Wq*QSCALE->g_Wq  2=Wk->g_Wk  3=Wv->g_Wv  4=Wo->g_Wo
// ---------------------------------------------------------------------------
__global__ __launch_bounds__(256)
void cvt_kernel(const float4* __restrict__ x,  const float4* __restrict__ wq,
                const float4* __restrict__ wk, const float4* __restrict__ wv,
                const float4* __restrict__ wo)
{
    const int z = blockIdx.z;
    const float4* src;
    float4* dst;
    int n4;
    float s = 1.0f;
    switch (z) {
        case 0: src = x;  dst = (float4*)g_X;  n4 = GM * GK / 4; break;
        case 1: src = wq; dst = (float4*)g_Wq; n4 = GN * GK / 4; s = 0.125f * LOG2E; break;
        case 2: src = wk; dst = (float4*)g_Wk; n4 = GN * GK / 4; break;
        case 3: src = wv; dst = (float4*)g_Wv; n4 = GN * GK / 4; break;
        default: src = wo; dst = (float4*)g_Wo; n4 = GN * GK / 4; break;
    }
    for (int i = blockIdx.x * 256 + threadIdx.x; i < n4; i += gridDim.x * 256) {
        float4 v = src[i];
        v.x = to_tf32(v.x * s); v.y = to_tf32(v.y * s);
        v.z = to_tf32(v.z * s); v.w = to_tf32(v.w * s);
        dst[i] = v;
    }
}

// ---------------------------------------------------------------------------
// TF32 GEMM: C = A[M,K] @ W[N,K]^T, inputs already tf32-formatted.
// CTA 128x128, 256 threads (8 warps 4x2), 3-stage cp.async pipeline, K-chunk 32.
// SMEM: 3 stages x (A 4096 + W 4096 floats), XOR-swizzled 32-float rows.
// ---------------------------------------------------------------------------
#define GEMM_SMEM (3 * 8192 * 4)

__global__ __launch_bounds__(256, 2)
void gemm_tc(const float* __restrict__ A,
             const float* __restrict__ W0, const float* __restrict__ W1,
             const float* __restrict__ W2,
             float* __restrict__ C0, float* __restrict__ C1, float* __restrict__ C2,
             int cvt_out)
{
    extern __shared__ float smf[];
    const uint32_t sb = smem_u32(smf);

    const float* W = (blockIdx.z == 0) ? W0 : (blockIdx.z == 1) ? W1 : W2;
    float*       C = (blockIdx.z == 0) ? C0 : (blockIdx.z == 1) ? C1 : C2;

    const int t    = threadIdx.x;
    const int w    = t >> 5;
    const int lane = t & 31;
    const int g    = lane >> 2;
    const int t4   = lane & 3;
    const int g4   = g << 2;
    const int m0   = (w >> 1) * 32;
    const int n0w  = (w & 1) * 64;
    const int bm   = blockIdx.y * 128;
    const int bn   = blockIdx.x * 128;

    // cp.async loader coords (4 iters x 256 thr covers 128x32 x2 tensors)
    const int lrow = (t * 4 + 0) >> 5;  // placeholder; explicit below

    float acc[2][8][4];
#pragma unroll
    for (int mf = 0; mf < 2; mf++)
#pragma unroll
        for (int nf = 0; nf < 8; nf++)
#pragma unroll
            for (int r = 0; r < 4; r++) acc[mf][nf][r] = 0.0f;

#define GEMM_ISSUE(CH) do {                                                   \
        const int _k0 = (CH) * 32;                                            \
        const uint32_t _sa = sb + ((CH) % 3) * 32768;                         \
        _Pragma("unroll")                                                     \
        for (int _i = 0; _i < 4; _i++) {                                      \
            int _idx = _i * 256 + t;                                          \
            int _row = _idx >> 3;                                             \
            int _f4  = (_idx & 7) * 4;                                        \
            uint32_t _o = (uint32_t)fswz32(_row * 32 + _f4) * 4;              \
            cp16(_sa + _o,        &A[(size_t)(bm + _row) * GK + _k0 + _f4]);  \
            cp16(_sa + 16384 + _o,&W[(size_t)(bn + _row) * GK + _k0 + _f4]);  \
        }                                                                     \
        cp_commit();                                                          \
    } while (0)

    GEMM_ISSUE(0);
    GEMM_ISSUE(1);

    for (int ch = 0; ch < 32; ch++) {
        if (ch + 2 < 32) {
            GEMM_ISSUE(ch + 2);
            asm volatile("cp.async.wait_group 2;" ::: "memory");
        } else if (ch + 1 < 32) {
            asm volatile("cp.async.wait_group 1;" ::: "memory");
        } else {
            asm volatile("cp.async.wait_group 0;" ::: "memory");
        }
        __syncthreads();

        const float* a_s = smf + (ch % 3) * 8192;
        const float* w_s = a_s + 4096;
#pragma unroll
        for (int ks = 0; ks < 4; ks++) {
            const int kc0 = (ks * 8 + t4) ^ g4;
            const int kc1 = kc0 ^ 4;
            float a[2][4];
#pragma unroll
            for (int mf = 0; mf < 2; mf++) {
                int r = m0 + mf * 16 + g;
                a[mf][0] = a_s[r * 32 + kc0];
                a[mf][1] = a_s[(r + 8) * 32 + kc0];
                a[mf][2] = a_s[r * 32 + kc1];
                a[mf][3] = a_s[(r + 8) * 32 + kc1];
            }
#pragma unroll
            for (int nf = 0; nf < 8; nf++) {
                int nr = n0w + nf * 8 + g;
                float b0 = w_s[nr * 32 + kc0];
                float b1 = w_s[nr * 32 + kc1];
                mma_tf32(acc[0][nf], a[0][0], a[0][1], a[0][2], a[0][3], b0, b1);
                mma_tf32(acc[1][nf], a[1][0], a[1][1], a[1][2], a[1][3], b0, b1);
            }
        }
        __syncthreads();
    }

    // epilogue
#pragma unroll
    for (int mf = 0; mf < 2; mf++) {
        int row = bm + m0 + mf * 16 + g;
#pragma unroll
        for (int nf = 0; nf < 8; nf++) {
            int col = bn + n0w + nf * 8 + 2 * t4;
            float v0 = acc[mf][nf][0], v1 = acc[mf][nf][1];
            float v2 = acc[mf][nf][2], v3 = acc[mf][nf][3];
            if (cvt_out) {
                v0 = to_tf32(v0); v1 = to_tf32(v1);
                v2 = to_tf32(v2); v3 = to_tf32(v3);
            }
            *(float2*)&C[(size_t)row * GN + col]       = make_float2(v0, v1);
            *(float2*)&C[(size_t)(row + 8) * GN + col] = make_float2(v2, v3);
        }
    }
#undef GEMM_ISSUE
}

// ---------------------------------------------------------------------------
// TF32 flash attention, exp2-domain online softmax.
// 128 threads (4 warps); CTA = 128 queries of one (b,h); warp = 32 query rows.
// KV streamed in 64-key tiles via cp.async. Q/K/V already tf32 (Q pre-scaled).
// SMEM floats: Q[128][64] @0, K[64][64] @8192, V[64][64] @12288,
//              P[128][64] @16384, madd[64] @24576.  Total 98,560 B.
// ---------------------------------------------------------------------------
#define ATT_SMEM ((24576 + 64) * 4)
#define QO 0
#define KO 8192
#define VO 12288
#define PO 16384

__global__ __launch_bounds__(128)
void attn_tc(const unsigned int* __restrict__ mask, float* __restrict__ out)
{
    extern __shared__ float smf[];
    const uint32_t sb = smem_u32(smf);
    float* madd = smf + 24576;

    const int t    = threadIdx.x;
    const int w    = t >> 5;
    const int lane = t & 31;
    const int g    = lane >> 2;
    const int t4   = lane & 3;
    const int g4   = g << 2;
    const int t44  = t4 << 2;
    const int t44b = (t4 + 4) << 2;
    const int q0   = blockIdx.x * 128;
    const int h    = blockIdx.y;
    const int b    = blockIdx.z;
    const int m0   = w * 32;

    const float BSC = ALPHA * LOG2E / (float)S_LEN;

    // Q tile -> smem (cp.async), swizzled
#pragma unroll
    for (int i = 0; i < 16; i++) {
        int idx = i * 128 + t;
        int row = idx >> 4;
        int f4  = (idx & 15) * 4;
        cp16(sb + (uint32_t)fswz64(QO + row * 64 + f4) * 4,
             &g_Q[((size_t)(b * S_LEN + q0 + row)) * E_DIM + h * D_HEAD + f4]);
    }
    cp_commit();

    float o[2][8][4];
#pragma unroll
    for (int mf = 0; mf < 2; mf++)
#pragma unroll
        for (int nf = 0; nf < 8; nf++)
#pragma unroll
            for (int r = 0; r < 4; r++) o[mf][nf][r] = 0.0f;

    float mrow[2][2] = {{-1e30f, -1e30f}, {-1e30f, -1e30f}};
    float lrow[2][2] = {{0.0f, 0.0f}, {0.0f, 0.0f}};
    float tgt[2][2];
#pragma unroll
    for (int mf = 0; mf < 2; mf++) {
        tgt[mf][0] = (float)(S_LEN - 1 - (q0 + m0 + mf * 16 + g));
        tgt[mf][1] = (float)(S_LEN - 1 - (q0 + m0 + mf * 16 + 8 + g));
    }

    for (int kt = 0; kt < S_LEN / 64; kt++) {
        const int k0g = kt * 64;
        __syncthreads();   // all warps done reading K/V of prev tile
#pragma unroll
        for (int i = 0; i < 8; i++) {
            int idx = i * 128 + t;
            int row = idx >> 4;
            int f4  = (idx & 15) * 4;
            size_t go = ((size_t)(b * S_LEN + k0g + row)) * E_DIM + h * D_HEAD + f4;
            uint32_t so = (uint32_t)fswz64(row * 64 + f4) * 4;
            cp16(sb + (KO * 4) + so, &g_K[go]);
            cp16(sb + (VO * 4) + so, &g_V[go]);
        }
        cp_commit();
        if (t < 64)
            madd[t] = (mask[b * S_LEN + k0g + t] != 0u) ? -1e30f : 0.0f;
        asm volatile("cp.async.wait_group 0;" ::: "memory");
        __syncthreads();

        // ---- S = Q @ K^T (exp2 domain) ----
        float sc[2][8][4];
#pragma unroll
        for (int mf = 0; mf < 2; mf++)
#pragma unroll
            for (int nf = 0; nf < 8; nf++)
#pragma unroll
                for (int r = 0; r < 4; r++) sc[mf][nf][r] = 0.0f;

#pragma unroll
        for (int ks = 0; ks < 8; ks++) {
            const int kc0 = (ks * 8 + t4) ^ g4;
            const int kc1 = kc0 ^ 4;
            float a[2][4];
#pragma unroll
            for (int mf = 0; mf < 2; mf++) {
                int r = m0 + mf * 16 + g;
                a[mf][0] = smf[QO + r * 64 + kc0];
                a[mf][1] = smf[QO + (r + 8) * 64 + kc0];
                a[mf][2] = smf[QO + r * 64 + kc1];
                a[mf][3] = smf[QO + (r + 8) * 64 + kc1];
            }
#pragma unroll
            for (int nf = 0; nf < 8; nf++) {
                int nr = nf * 8 + g;
                float b0 = smf[KO + nr * 64 + kc0];
                float b1 = smf[KO + nr * 64 + kc1];
                mma_tf32(sc[0][nf], a[0][0], a[0][1], a[0][2], a[0][3], b0, b1);
                mma_tf32(sc[1][nf], a[1][0], a[1][1], a[1][2], a[1][3], b0, b1);
            }
        }

        // ---- bias + mask + online softmax + P store ----
#pragma unroll
        for (int mf = 0; mf < 2; mf++) {
#pragma unroll
            for (int nf = 0; nf < 8; nf++) {
                int jc = nf * 8 + 2 * t4;
                float jk0 = (float)(k0g + jc);
                float ma0 = madd[jc], ma1 = madd[jc + 1];
                sc[mf][nf][0] += -BSC * fabsf(jk0 - tgt[mf][0]) + ma0;
                sc[mf][nf][1] += -BSC * fabsf(jk0 + 1.0f - tgt[mf][0]) + ma1;
                sc[mf][nf][2] += -BSC * fabsf(jk0 - tgt[mf][1]) + ma0;
                sc[mf][nf][3] += -BSC * fabsf(jk0 + 1.0f - tgt[mf][1]) + ma1;
            }
            float mx0 = -1e30f, mx1 = -1e30f;
#pragma unroll
            for (int nf = 0; nf < 8; nf++) {
                mx0 = fmaxf(mx0, fmaxf(sc[mf][nf][0], sc[mf][nf][1]));
                mx1 = fmaxf(mx1, fmaxf(sc[mf][nf][2], sc[mf][nf][3]));
            }
            mx0 = fmaxf(mx0, __shfl_xor_sync(0xffffffffu, mx0, 1));
            mx0 = fmaxf(mx0, __shfl_xor_sync(0xffffffffu, mx0, 2));
            mx1 = fmaxf(mx1, __shfl_xor_sync(0xffffffffu, mx1, 1));
            mx1 = fmaxf(mx1, __shfl_xor_sync(0xffffffffu, mx1, 2));

            float mnew0 = fmaxf(mrow[mf][0], mx0);
            float mnew1 = fmaxf(mrow[mf][1], mx1);
            float c0 = ex2(mrow[mf][0] - mnew0);
            float c1 = ex2(mrow[mf][1] - mnew1);
            mrow[mf][0] = mnew0; mrow[mf][1] = mnew1;

            float s0 = 0.0f, s1 = 0.0f;
            int r = m0 + mf * 16 + g;
#pragma unroll
            for (int nf = 0; nf < 8; nf++) {
                float p0 = ex2(sc[mf][nf][0] - mnew0);
                float p1 = ex2(sc[mf][nf][1] - mnew0);
                float p2 = ex2(sc[mf][nf][2] - mnew1);
                float p3 = ex2(sc[mf][nf][3] - mnew1);
                s0 += p0 + p1;
                s1 += p2 + p3;
                int colx = (nf * 8 + 2 * t4) ^ g4;
                *(float2*)&smf[PO + r * 64 + colx]       = make_float2(to_tf32(p0), to_tf32(p1));
                *(float2*)&smf[PO + (r + 8) * 64 + colx] = make_float2(to_tf32(p2), to_tf32(p3));
            }
            s0 += __shfl_xor_sync(0xffffffffu, s0, 1);
            s0 += __shfl_xor_sync(0xffffffffu, s0, 2);
            s1 += __shfl_xor_sync(0xffffffffu, s1, 1);
            s1 += __shfl_xor_sync(0xffffffffu, s1, 2);
            lrow[mf][0] = lrow[mf][0] * c0 + s0;
            lrow[mf][1] = lrow[mf][1] * c1 + s1;
#pragma unroll
            for (int nf = 0; nf < 8; nf++) {
                o[mf][nf][0] *= c0; o[mf][nf][1] *= c0;
                o[mf][nf][2] *= c1; o[mf][nf][3] *= c1;
            }
        }
        __syncwarp();

        // ---- O += P @ V ----
#pragma unroll
        for (int ks = 0; ks < 8; ks++) {
            const int k0 = ks * 8;
            const int kc0 = (k0 + t4) ^ g4;
            const int kc1 = kc0 ^ 4;
            float a[2][4];
#pragma unroll
            for (int mf = 0; mf < 2; mf++) {
                int r = m0 + mf * 16 + g;
                a[mf][0] = smf[PO + r * 64 + kc0];
                a[mf][1] = smf[PO + (r + 8) * 64 + kc0];
                a[mf][2] = smf[PO + r * 64 + kc1];
                a[mf][3] = smf[PO + (r + 8) * 64 + kc1];
            }
#pragma unroll
            for (int nf = 0; nf < 8; nf++) {
                int n0 = nf * 8 + g;
                float b0 = smf[VO + (k0 + t4) * 64 + (n0 ^ t44)];
                float b1 = smf[VO + (k0 + t4 + 4) * 64 + (n0 ^ t44b)];
                mma_tf32(o[0][nf], a[0][0], a[0][1], a[0][2], a[0][3], b0, b1);
                mma_tf32(o[1][nf], a[1][0], a[1][1], a[1][2], a[1][3], b0, b1);
            }
        }
        __syncwarp();
    }

    // ---- finalize (write tf32 so O-proj can cp.async raw) ----
#pragma unroll
    for (int mf = 0; mf < 2; mf++) {
        float inv0 = 1.0f / lrow[mf][0];
        float inv1 = 1.0f / lrow[mf][1];
        size_t r0 = ((size_t)(b * S_LEN + q0 + m0 + mf * 16 + g)) * E_DIM + h * D_HEAD;
        size_t r1 = r0 + 8 * E_DIM;
#pragma unroll
        for (int nf = 0; nf < 8; nf++) {
            int col = nf * 8 + 2 * t4;
            *(float2*)&out[r0 + col] =
                make_float2(to_tf32(o[mf][nf][0] * inv0), to_tf32(o[mf][nf][1] * inv0));
            *(float2*)&out[r1 + col] =
                make_float2(to_tf32(o[mf][nf][2] * inv1), to_tf32(o[mf][nf][3] * inv1));
        }
    }
}

// ---------------------------------------------------------------------------
extern "C" void kernel_launch(void* const* d_in, const int* in_sizes, int n_in,
                              void* d_out, int out_size)
{
    const float* x    = (const float*)d_in[0];
    const float* Wq   = (const float*)d_in[1];
    const float* Wk   = (const float*)d_in[2];
    const float* Wv   = (const float*)d_in[3];
    const float* Wo   = (const float*)d_in[4];
    const unsigned int* mask = (const unsigned int*)d_in[5];
    float* out = (float*)d_out;

    float *xp, *wqp, *wkp, *wvp, *wop, *qp, *kp, *vp, *ap;
    cudaGetSymbolAddress((void**)&xp,  g_X);
    cudaGetSymbolAddress((void**)&wqp, g_Wq);
    cudaGetSymbolAddress((void**)&wkp, g_Wk);
    cudaGetSymbolAddress((void**)&wvp, g_Wv);
    cudaGetSymbolAddress((void**)&wop, g_Wo);
    cudaGetSymbolAddress((void**)&qp,  g_Q);
    cudaGetSymbolAddress((void**)&kp,  g_K);
    cudaGetSymbolAddress((void**)&vp,  g_V);
    cudaGetSymbolAddress((void**)&ap,  g_A);

    cudaFuncSetAttribute(gemm_tc, cudaFuncAttributeMaxDynamicSharedMemorySize, GEMM_SMEM);
    cudaFuncSetAttribute(attn_tc, cudaFuncAttributeMaxDynamicSharedMemorySize, ATT_SMEM);

    // 1. pre-convert inputs to tf32 (Wq scaled by 0.125*log2e)
    cvt_kernel<<<dim3(512, 1, 5), 256>>>((const float4*)x, (const float4*)Wq,
                                         (const float4*)Wk, (const float4*)Wv,
                                         (const float4*)Wo);

    // 2. fused QKV projections
    gemm_tc<<<dim3(GN / 128, GM / 128, 3), 256, GEMM_SMEM>>>(
        xp, wqp, wkp, wvp, qp, kp, vp, 1);

    // 3. attention
    attn_tc<<<dim3(S_LEN / 128, H_NUM, B_SZ), 128, ATT_SMEM>>>(mask, ap);

    // 4. output projection (fp32 out)
    gemm_tc<<<dim3(GN / 128, GM / 128, 1), 256, GEMM_SMEM>>>(
        ap, wop, wop, wop, out, out, out, 0);
}